// round 13
// baseline (speedup 1.0000x reference)
#include <cuda_runtime.h>
#include <cuda_fp16.h>
#include <math.h>
#include <stdint.h>

// ---------------- problem constants ----------------
#define NB   8
#define LSEQ 1024
#define SSEQ 2048
#define DIM  512
#define TOKD 256
#define KIN  1280
#define TOKS 10240

// ---------------- scratch ----------------
__device__ __align__(256) __half g_WcH  [DIM * KIN];
__device__ __align__(256) __half g_WrH  [4 * DIM * DIM];   // [Wlat, Wvlat, Wtok, Wvtok]
__device__ __align__(256) __half g_toksH[NB * TOKS * TOKD];
__device__ __align__(256) __half g_latH [NB * LSEQ * DIM];
__device__ __align__(256) float  g_tok  [NB * SSEQ * DIM];
__device__ __align__(256) __half g_tokH [NB * SSEQ * DIM];
__device__ __align__(256) __half g_RlatH[NB * LSEQ * DIM];
__device__ __align__(256) __half g_RtokH[NB * SSEQ * DIM];
__device__ __align__(256) __half g_VlatT[NB * DIM * LSEQ];   // (E, L)
__device__ __align__(256) __half g_VtokT[NB * DIM * SSEQ];   // (E, S)
__device__ __align__(256) float  g_S    [NB * LSEQ * SSEQ];
__device__ __align__(256) __half g_PrH  [NB * LSEQ * SSEQ];
__device__ __align__(256) __half g_PcTH [NB * SSEQ * LSEQ];
__device__ __align__(256) float  g_rmax [NB * LSEQ];
__device__ __align__(256) float  g_rinv [NB * LSEQ];
__device__ __align__(256) float  g_cmax [NB * SSEQ];
__device__ __align__(256) float  g_cinv [NB * SSEQ];
__device__ __align__(256) float  g_prm  [NB * 16 * LSEQ];
__device__ __align__(256) float  g_prs  [NB * 16 * LSEQ];
__device__ __align__(256) float  g_pcm  [NB * 8 * SSEQ];
__device__ __align__(256) float  g_pcs  [NB * 8 * SSEQ];

// ---------------- GEMM config: 128x128 block, 8 warps (64x32 warp tiles) ----------------
#define BM 128
#define BN 128
#define BK 32
#define PH 40
#define STAGES 4
#define ASZH (BM * PH)
#define BSZH (BN * PH)
#define SM_BYTES (STAGES * (ASZH + BSZH) * 2)   // 81920
#define TSTR 136

__device__ __forceinline__ void mma_f16(float c[4], const uint32_t a[4], const uint32_t b[2]) {
    asm volatile(
        "mma.sync.aligned.m16n8k16.row.col.f32.f16.f16.f32 "
        "{%0,%1,%2,%3}, {%4,%5,%6,%7}, {%8,%9}, {%0,%1,%2,%3};"
        : "+f"(c[0]), "+f"(c[1]), "+f"(c[2]), "+f"(c[3])
        : "r"(a[0]), "r"(a[1]), "r"(a[2]), "r"(a[3]), "r"(b[0]), "r"(b[1]));
}

__device__ __forceinline__ void ldsm_x4(uint32_t r[4], uint32_t addr) {
    asm volatile("ldmatrix.sync.aligned.m8n8.x4.shared.b16 {%0,%1,%2,%3}, [%4];"
                 : "=r"(r[0]), "=r"(r[1]), "=r"(r[2]), "=r"(r[3]) : "r"(addr));
}

__device__ __forceinline__ void cpasync16(uint32_t dst, const void* src) {
    asm volatile("cp.async.cg.shared.global [%0], [%1], 16;" :: "r"(dst), "l"(src));
}

__device__ __forceinline__ void msmerge(float& m, float& s, float om, float os) {
    float M = fmaxf(m, om);
    s = s * __expf(m - M) + os * __expf(om - M);
    m = M;
}

// ---------------- shared GEMM mainloop (256 threads) ----------------
__device__ __forceinline__ void gemm_core(
    const __half* __restrict__ A, const __half* __restrict__ B,
    int lda, int ldb, int tiles, int m0, int n0, float (&acc)[4][4][4])
{
    extern __shared__ __half smh[];
    const uint32_t sbase = (uint32_t)__cvta_generic_to_shared(smh);
    const uint32_t aReg = sbase;
    const uint32_t bReg = sbase + STAGES * ASZH * 2;
    const int tid = threadIdx.x;
    const int wid = tid >> 5, lane = tid & 31;
    const int wm = (wid >> 2) * 64, wn = (wid & 3) * 32;

    uint32_t aAddr[4], bAddr[2];
    {
        const int r = lane & 7;
        const int aRowOff = ((lane >> 3) & 1) * 8 + r;
        const int aChunk = lane >> 4;
#pragma unroll
        for (int mi = 0; mi < 4; mi++)
            aAddr[mi] = aReg + (uint32_t)((wm + mi * 16 + aRowOff) * PH + aChunk * 8) * 2;
        const int bRow = (lane >> 4);
        const int bChunk = (lane >> 3) & 1;
#pragma unroll
        for (int p = 0; p < 2; p++)
            bAddr[p] = bReg + (uint32_t)((wn + (2 * p + bRow) * 8 + r) * PH + bChunk * 8) * 2;
    }

#pragma unroll
    for (int i = 0; i < 4; i++)
#pragma unroll
        for (int j = 0; j < 4; j++)
#pragma unroll
            for (int r = 0; r < 4; r++) acc[i][j][r] = 0.f;

    auto loadTile = [&](int t, int buf) {
        const int k0 = t * BK;
        const uint32_t Ab = aReg + buf * ASZH * 2;
        const uint32_t Bb = bReg + buf * BSZH * 2;
#pragma unroll
        for (int i = 0; i < 2; i++) {
            int idx = i * 256 + tid;
            int row = idx >> 2, seg = idx & 3;
            cpasync16(Ab + (uint32_t)(row * PH + seg * 8) * 2,
                      A + (long long)(m0 + row) * lda + k0 + seg * 8);
        }
#pragma unroll
        for (int i = 0; i < 2; i++) {
            int idx = i * 256 + tid;
            int row = idx >> 2, seg = idx & 3;
            cpasync16(Bb + (uint32_t)(row * PH + seg * 8) * 2,
                      B + (long long)(n0 + row) * ldb + k0 + seg * 8);
        }
        asm volatile("cp.async.commit_group;");
    };

    auto compute = [&](int buf) {
        const uint32_t aOff = buf * ASZH * 2;
        const uint32_t bOff = buf * BSZH * 2;
#pragma unroll
        for (int ks = 0; ks < 2; ks++) {
            uint32_t af[4][4], bf[4][2];
#pragma unroll
            for (int mi = 0; mi < 4; mi++)
                ldsm_x4(af[mi], aAddr[mi] + aOff + ks * 32);
#pragma unroll
            for (int p = 0; p < 2; p++) {
                uint32_t t4[4];
                ldsm_x4(t4, bAddr[p] + bOff + ks * 32);
                bf[2 * p][0] = t4[0]; bf[2 * p][1] = t4[1];
                bf[2 * p + 1][0] = t4[2]; bf[2 * p + 1][1] = t4[3];
            }
#pragma unroll
            for (int mi = 0; mi < 4; mi++)
#pragma unroll
                for (int ni = 0; ni < 4; ni++)
                    mma_f16(acc[mi][ni], af[mi], bf[ni]);
        }
    };

    loadTile(0, 0);
    loadTile(1, 1);
    loadTile(2, 2);
    for (int t = 0; t < tiles; t++) {
        if (t + 2 < tiles) asm volatile("cp.async.wait_group 2;");
        else               asm volatile("cp.async.wait_group 0;");
        __syncthreads();
        if (t + 3 < tiles) loadTile(t + 3, (t + 3) & 3);
        compute(t & 3);
    }
}

// ---------------- conv GEMM ----------------
__global__ __launch_bounds__(256, 2) void k_conv(
    const __half* __restrict__ A, const __half* __restrict__ B,
    float* __restrict__ Cf, __half* __restrict__ Ch, const float* __restrict__ bias)
{
    const int m0 = blockIdx.y * BM, n0 = blockIdx.x * BN;
    float acc[4][4][4];
    gemm_core(A, B, KIN, KIN, KIN / BK, m0, n0, acc);
    const int tid = threadIdx.x, wid = tid >> 5, lane = tid & 31;
    const int grp = lane >> 2, tig = lane & 3;
    const int wm = (wid >> 2) * 64, wn = (wid & 3) * 32;
#pragma unroll
    for (int mi = 0; mi < 4; mi++) {
        const int r = m0 + wm + mi * 16 + grp;
#pragma unroll
        for (int ni = 0; ni < 4; ni++) {
            const int c = n0 + wn + ni * 8 + tig * 2;
            float bx = bias[c], by = bias[c + 1];
            float2 v0 = {acc[mi][ni][0] + bx, acc[mi][ni][1] + by};
            float2 v1 = {acc[mi][ni][2] + bx, acc[mi][ni][3] + by};
            *(float2*)(Cf + (long long)r * DIM + c) = v0;
            *(float2*)(Cf + (long long)(r + 8) * DIM + c) = v1;
            *(__half2*)(Ch + (long long)r * DIM + c) = __floats2half2_rn(v0.x, v0.y);
            *(__half2*)(Ch + (long long)(r + 8) * DIM + c) = __floats2half2_rn(v1.x, v1.y);
        }
    }
}

// ---------------- merged R/V projection, V written transposed ----------------
__global__ __launch_bounds__(256, 2) void k_proj(
    const __half* __restrict__ A, const __half* __restrict__ W,
    __half* __restrict__ Rdst, __half* __restrict__ VTdst, int seq)
{
    const int m0 = blockIdx.y * BM, n0 = blockIdx.x * BN;
    float acc[4][4][4];
    gemm_core(A, W, DIM, DIM, DIM / BK, m0, n0, acc);
    const int tid = threadIdx.x, wid = tid >> 5, lane = tid & 31;
    const int grp = lane >> 2, tig = lane & 3;
    const int wm = (wid >> 2) * 64, wn = (wid & 3) * 32;

    if (n0 < DIM) {
#pragma unroll
        for (int mi = 0; mi < 4; mi++) {
            const int r = m0 + wm + mi * 16 + grp;
#pragma unroll
            for (int ni = 0; ni < 4; ni++) {
                const int c = n0 + wn + ni * 8 + tig * 2;
                *(__half2*)(Rdst + (long long)r * DIM + c) =
                    __floats2half2_rn(acc[mi][ni][0], acc[mi][ni][1]);
                *(__half2*)(Rdst + (long long)(r + 8) * DIM + c) =
                    __floats2half2_rn(acc[mi][ni][2], acc[mi][ni][3]);
            }
        }
    } else {
        extern __shared__ __half smh[];
        __syncthreads();
        __half* st = smh;
#pragma unroll
        for (int mi = 0; mi < 4; mi++) {
            const int ml = wm + mi * 16 + grp;
#pragma unroll
            for (int ni = 0; ni < 4; ni++) {
                const int cl = wn + ni * 8 + tig * 2;
                st[(cl + 0) * TSTR + ml]     = __float2half_rn(acc[mi][ni][0]);
                st[(cl + 1) * TSTR + ml]     = __float2half_rn(acc[mi][ni][1]);
                st[(cl + 0) * TSTR + ml + 8] = __float2half_rn(acc[mi][ni][2]);
                st[(cl + 1) * TSTR + ml + 8] = __float2half_rn(acc[mi][ni][3]);
            }
        }
        __syncthreads();
        const int b = m0 / seq;
        const int s0 = m0 - b * seq;
        const int e0 = n0 - DIM;
        __half* VT = VTdst + (long long)b * DIM * seq;
#pragma unroll
        for (int i = 0; i < 32; i++) {
            int idx = i * 256 + tid;
            int cl = idx >> 6, pos = (idx & 63) * 2;
            __half2 v = *(__half2*)(st + cl * TSTR + pos);
            *(__half2*)(VT + (long long)(e0 + cl) * seq + s0 + pos) = v;
        }
    }
}

// ---------------- scores GEMM + fused tile-partial stats ----------------
__global__ __launch_bounds__(256, 2) void k_scores(
    const __half* __restrict__ Aall, const __half* __restrict__ Ball, float alpha)
{
    const long long z = blockIdx.z;
    const __half* A = Aall + z * (long long)LSEQ * DIM;
    const __half* B = Ball + z * (long long)SSEQ * DIM;
    float* Cf = g_S + z * (long long)LSEQ * SSEQ;
    const int m0 = blockIdx.y * BM, n0 = blockIdx.x * BN;

    float acc[4][4][4];
    gemm_core(A, B, DIM, DIM, DIM / BK, m0, n0, acc);

    const int tid = threadIdx.x, wid = tid >> 5, lane = tid & 31;
    const int grp = lane >> 2, tig = lane & 3;
    const int wm = (wid >> 2) * 64, wn = (wid & 3) * 32;

#pragma unroll
    for (int mi = 0; mi < 4; mi++)
#pragma unroll
        for (int ni = 0; ni < 4; ni++)
#pragma unroll
            for (int r = 0; r < 4; r++) acc[mi][ni][r] *= alpha;
#pragma unroll
    for (int mi = 0; mi < 4; mi++) {
        const int r = m0 + wm + mi * 16 + grp;
#pragma unroll
        for (int ni = 0; ni < 4; ni++) {
            const int c = n0 + wn + ni * 8 + tig * 2;
            *(float2*)(Cf + (long long)r * SSEQ + c) = make_float2(acc[mi][ni][0], acc[mi][ni][1]);
            *(float2*)(Cf + (long long)(r + 8) * SSEQ + c) = make_float2(acc[mi][ni][2], acc[mi][ni][3]);
        }
    }
    extern __shared__ __half smh[];
    float* smr = (float*)smh;            // row partials: [8 warps][64 rows][2]
    float* smc = smr + 8 * 64 * 2;       // col partials: [8 warps][32 cols][2]
    __syncthreads();
    // ---- row partials (each warp: 64 rows x 32 cols) ----
#pragma unroll
    for (int mi = 0; mi < 4; mi++) {
#pragma unroll
        for (int h = 0; h < 2; h++) {
            float m = -1e30f;
#pragma unroll
            for (int ni = 0; ni < 4; ni++) {
                m = fmaxf(m, acc[mi][ni][2 * h]);
                m = fmaxf(m, acc[mi][ni][2 * h + 1]);
            }
            float s = 0.f;
#pragma unroll
            for (int ni = 0; ni < 4; ni++) {
                s += __expf(acc[mi][ni][2 * h] - m);
                s += __expf(acc[mi][ni][2 * h + 1] - m);
            }
#pragma unroll
            for (int off = 1; off <= 2; off <<= 1) {
                float om = __shfl_xor_sync(0xffffffffu, m, off);
                float os = __shfl_xor_sync(0xffffffffu, s, off);
                msmerge(m, s, om, os);
            }
            if (tig == 0) {
                int lr = mi * 16 + grp + 8 * h;       // 0..63
                smr[(wid * 64 + lr) * 2 + 0] = m;
                smr[(wid * 64 + lr) * 2 + 1] = s;
            }
        }
    }
    // ---- col partials (each warp: 32 cols x 64 rows) ----
#pragma unroll
    for (int ni = 0; ni < 4; ni++) {
#pragma unroll
        for (int j = 0; j < 2; j++) {
            float m = -1e30f;
#pragma unroll
            for (int mi = 0; mi < 4; mi++) {
                m = fmaxf(m, acc[mi][ni][j]);
                m = fmaxf(m, acc[mi][ni][2 + j]);
            }
            float s = 0.f;
#pragma unroll
            for (int mi = 0; mi < 4; mi++) {
                s += __expf(acc[mi][ni][j] - m);
                s += __expf(acc[mi][ni][2 + j] - m);
            }
#pragma unroll
            for (int off = 4; off <= 16; off <<= 1) {
                float om = __shfl_xor_sync(0xffffffffu, m, off);
                float os = __shfl_xor_sync(0xffffffffu, s, off);
                msmerge(m, s, om, os);
            }
            if (grp == 0) {
                int lc = ni * 8 + tig * 2 + j;        // 0..31
                smc[(wid * 32 + lc) * 2 + 0] = m;
                smc[(wid * 32 + lc) * 2 + 1] = s;
            }
        }
    }
    __syncthreads();
    if (tid < 128) {
        // rows: row r covered by warps w0..w0+3 (w0 = (r>>6)*4)
        const int r = tid;
        const int w0 = (r >> 6) * 4, lr = r & 63;
        float m = smr[((w0 + 0) * 64 + lr) * 2 + 0];
        float s = smr[((w0 + 0) * 64 + lr) * 2 + 1];
#pragma unroll
        for (int k = 1; k < 4; k++)
            msmerge(m, s, smr[((w0 + k) * 64 + lr) * 2 + 0], smr[((w0 + k) * 64 + lr) * 2 + 1]);
        const long long idx = (z * 16 + blockIdx.x) * LSEQ + m0 + r;
        g_prm[idx] = m;
        g_prs[idx] = s;
    } else {
        // cols: col c covered by warps (c>>5) and (c>>5)+4
        const int c = tid - 128;
        const int w1 = c >> 5, lc = c & 31;
        float m = smc[((w1) * 32 + lc) * 2 + 0];
        float s = smc[((w1) * 32 + lc) * 2 + 1];
        msmerge(m, s, smc[((w1 + 4) * 32 + lc) * 2 + 0], smc[((w1 + 4) * 32 + lc) * 2 + 1]);
        const long long idx = (z * 8 + blockIdx.y) * SSEQ + n0 + c;
        g_pcm[idx] = m;
        g_pcs[idx] = s;
    }
}

// ---------------- merged delta GEMM ----------------
__global__ __launch_bounds__(256, 2) void k_delta(
    const float* __restrict__ latents, float* __restrict__ out)
{
    constexpr long long UL = (long long)NB * LSEQ * DIM;
    constexpr long long UT = (long long)NB * SSEQ * DIM;
    constexpr long long CONCAT = UL + UT;

    const long long z = blockIdx.z;
    const __half *A, *Bm;
    const float* addend;
    float *Cf, *Cf2;
    int lda, K, m0;
    if (blockIdx.y < 8) {
        A = g_PrH + z * (long long)LSEQ * SSEQ;  lda = SSEQ; K = SSEQ;
        Bm = g_VtokT + z * (long long)DIM * SSEQ;
        addend = latents + z * (long long)LSEQ * DIM;
        Cf = out + z * (long long)LSEQ * DIM;
        Cf2 = out + CONCAT + z * (long long)(LSEQ + SSEQ) * DIM;
        m0 = blockIdx.y * BM;
    } else {
        A = g_PcTH + z * (long long)SSEQ * LSEQ; lda = LSEQ; K = LSEQ;
        Bm = g_VlatT + z * (long long)DIM * LSEQ;
        addend = g_tok + z * (long long)SSEQ * DIM;
        Cf = out + UL + z * (long long)SSEQ * DIM;
        Cf2 = out + CONCAT + (long long)LSEQ * DIM + z * (long long)(LSEQ + SSEQ) * DIM;
        m0 = (blockIdx.y - 8) * BM;
    }
    const int n0 = blockIdx.x * BN;

    float acc[4][4][4];
    gemm_core(A, Bm, lda, lda, K / BK, m0, n0, acc);

    const int tid = threadIdx.x, wid = tid >> 5, lane = tid & 31;
    const int grp = lane >> 2, tig = lane & 3;
    const int wm = (wid >> 2) * 64, wn = (wid & 3) * 32;
#pragma unroll
    for (int mi = 0; mi < 4; mi++) {
        const int r = m0 + wm + mi * 16 + grp;
#pragma unroll
        for (int ni = 0; ni < 4; ni++) {
            const int c = n0 + wn + ni * 8 + tig * 2;
            float2 a0 = *(const float2*)(addend + (long long)r * DIM + c);
            float2 a1 = *(const float2*)(addend + (long long)(r + 8) * DIM + c);
            float2 v0 = {acc[mi][ni][0] + a0.x, acc[mi][ni][1] + a0.y};
            float2 v1 = {acc[mi][ni][2] + a1.x, acc[mi][ni][3] + a1.y};
            *(float2*)(Cf  + (long long)r * DIM + c) = v0;
            *(float2*)(Cf  + (long long)(r + 8) * DIM + c) = v1;
            *(float2*)(Cf2 + (long long)r * DIM + c) = v0;
            *(float2*)(Cf2 + (long long)(r + 8) * DIM + c) = v1;
        }
    }
}

// ---------------- prep kernels ----------------
__global__ void k_prep_w(const float* __restrict__ w, __half* __restrict__ wc) {
    int i = blockIdx.x * 256 + threadIdx.x;
    if (i < DIM * KIN) {
        int e = i / KIN;
        int r = i - e * KIN;
        int t = r / TOKD;
        int c = r - t * TOKD;
        wc[i] = __float2half_rn(w[e * KIN + c * 5 + t]);
    }
}
__global__ void k_prep_wr(const float* __restrict__ w0, const float* __restrict__ w1,
                          const float* __restrict__ w2, const float* __restrict__ w3,
                          __half* __restrict__ out) {
    int i = blockIdx.x * 256 + threadIdx.x;
    if (i < DIM * DIM) {
        out[i]                 = __float2half_rn(w0[i]);
        out[i + DIM * DIM]     = __float2half_rn(w1[i]);
        out[i + 2 * DIM * DIM] = __float2half_rn(w2[i]);
        out[i + 3 * DIM * DIM] = __float2half_rn(w3[i]);
    }
}
__global__ void k_tohalf(const float* __restrict__ s, __half* __restrict__ d, long long n) {
    long long i = ((long long)blockIdx.x * 256 + threadIdx.x) * 4;
    if (i < n) {
        float4 v = *(const float4*)(s + i);
        *(__half2*)(d + i)     = __floats2half2_rn(v.x, v.y);
        *(__half2*)(d + i + 2) = __floats2half2_rn(v.z, v.w);
    }
}

// ---------------- merged stat combine ----------------
__global__ void k_comb(float* __restrict__ rmax, float* __restrict__ rinv,
                       float* __restrict__ cmax, float* __restrict__ cinv) {
    const int idx = blockIdx.x * 256 + threadIdx.x;
    if (idx < NB * LSEQ) {
        const int b = idx >> 10, l = idx & 1023;
        float m = -1e30f;
#pragma unroll
        for (int t = 0; t < 16; t++) m = fmaxf(m, g_prm[(b * 16 + t) * LSEQ + l]);
        float s = 0.f;
#pragma unroll
        for (int t = 0; t < 16; t++)
            s += g_prs[(b * 16 + t) * LSEQ + l] * __expf(g_prm[(b * 16 + t) * LSEQ + l] - m);
        rmax[idx] = m;
        rinv[idx] = 1.f / s;
    } else {
        const int j = idx - NB * LSEQ;
        const int b = j >> 11, s0 = j & 2047;
        float m = -1e30f;
#pragma unroll
        for (int t = 0; t < 8; t++) m = fmaxf(m, g_pcm[(b * 8 + t) * SSEQ + s0]);
        float s = 0.f;
#pragma unroll
        for (int t = 0; t < 8; t++)
            s += g_pcs[(b * 8 + t) * SSEQ + s0] * __expf(g_pcm[(b * 8 + t) * SSEQ + s0] - m);
        cmax[j] = m;
        cinv[j] = 1.f / s;
    }
}

// ---------------- apply both softmaxes -> half (vectorized) ----------------
__global__ __launch_bounds__(256) void k_softmax_apply(
    const float* __restrict__ A, __half* __restrict__ Pr, __half* __restrict__ PcT,
    const float* __restrict__ rmax, const float* __restrict__ rinv,
    const float* __restrict__ cmax, const float* __restrict__ cinv)
{
    __shared__ float tile[64][33];
    const int b = blockIdx.z;
    const int s0 = blockIdx.x * 64, l0 = blockIdx.y * 32;
    const float* Ab = A + (long long)b * LSEQ * SSEQ;
    __half* Prb = Pr + (long long)b * LSEQ * SSEQ;
    __half* Pcb = PcT + (long long)b * SSEQ * LSEQ;
    const int lane = threadIdx.x & 31, ty = threadIdx.x >> 5;

    const int sc = s0 + 2 * lane;
    const float2 cm = *(const float2*)(cmax + b * SSEQ + sc);
    const float2 ci = *(const float2*)(cinv + b * SSEQ + sc);
#pragma unroll
    for (int i = 0; i < 4; i++) {
        const int l = l0 + ty + i * 8;
        const float rm = rmax[b * LSEQ + l];
        const float riv = rinv[b * LSEQ + l];
        float2 v = *(const float2*)(Ab + (long long)l * SSEQ + sc);
        *(__half2*)(Prb + (long long)l * SSEQ + sc) =
            __floats2half2_rn(__expf(v.x - rm) * riv, __expf(v.y - rm) * riv);
        tile[2 * lane][ty + i * 8]     = __expf(v.x - cm.x) * ci.x;
        tile[2 * lane + 1][ty + i * 8] = __expf(v.y - cm.y) * ci.y;
    }
    __syncthreads();
    const int sl = threadIdx.x >> 2;
    const int lo = (threadIdx.x & 3) * 8;
    __half* dst = Pcb + (long long)(s0 + sl) * LSEQ + l0 + lo;
#pragma unroll
    for (int j = 0; j < 8; j += 2)
        *(__half2*)(dst + j) = __floats2half2_rn(tile[sl][lo + j], tile[sl][lo + j + 1]);
}

// ---------------- launch ----------------
extern "C" void kernel_launch(void* const* d_in, const int* in_sizes, int n_in,
                              void* d_out, int out_size) {
    const float* latents = (const float*)d_in[0];
    const float* tokens  = (const float*)d_in[1];
    const float* W_lat   = (const float*)d_in[2];
    const float* W_tok   = (const float*)d_in[3];
    const float* W_vlat  = (const float*)d_in[4];
    const float* W_vtok  = (const float*)d_in[5];
    const float* conv_w  = (const float*)d_in[6];
    const float* conv_b  = (const float*)d_in[7];
    float* out = (float*)d_out;

    __half *wcH, *wrH, *toksH, *latH, *tokH, *rlatH, *rtokH, *vlatT, *vtokT, *prH, *pcTH;
    float *tok, *smat, *rmax, *rinv, *cmax, *cinv;
    cudaGetSymbolAddress((void**)&wcH,   g_WcH);
    cudaGetSymbolAddress((void**)&wrH,   g_WrH);
    cudaGetSymbolAddress((void**)&toksH, g_toksH);
    cudaGetSymbolAddress((void**)&latH,  g_latH);
    cudaGetSymbolAddress((void**)&tok,   g_tok);
    cudaGetSymbolAddress((void**)&tokH,  g_tokH);
    cudaGetSymbolAddress((void**)&rlatH, g_RlatH);
    cudaGetSymbolAddress((void**)&rtokH, g_RtokH);
    cudaGetSymbolAddress((void**)&vlatT, g_VlatT);
    cudaGetSymbolAddress((void**)&vtokT, g_VtokT);
    cudaGetSymbolAddress((void**)&prH,   g_PrH);
    cudaGetSymbolAddress((void**)&pcTH,  g_PcTH);
    cudaGetSymbolAddress((void**)&smat,  g_S);
    cudaGetSymbolAddress((void**)&rmax,  g_rmax);
    cudaGetSymbolAddress((void**)&rinv,  g_rinv);
    cudaGetSymbolAddress((void**)&cmax,  g_cmax);
    cudaGetSymbolAddress((void**)&cinv,  g_cinv);

    cudaFuncSetAttribute(k_conv,   cudaFuncAttributeMaxDynamicSharedMemorySize, SM_BYTES);
    cudaFuncSetAttribute(k_proj,   cudaFuncAttributeMaxDynamicSharedMemorySize, SM_BYTES);
    cudaFuncSetAttribute(k_scores, cudaFuncAttributeMaxDynamicSharedMemorySize, SM_BYTES);
    cudaFuncSetAttribute(k_delta,  cudaFuncAttributeMaxDynamicSharedMemorySize, SM_BYTES);

    static cudaStream_t s1 = nullptr;
    static cudaEvent_t eRoot = nullptr, eA = nullptr, eB = nullptr;
    if (s1 == nullptr) {
        cudaStreamCreateWithFlags(&s1, cudaStreamNonBlocking);
        cudaEventCreateWithFlags(&eRoot, cudaEventDisableTiming);
        cudaEventCreateWithFlags(&eA, cudaEventDisableTiming);
        cudaEventCreateWithFlags(&eB, cudaEventDisableTiming);
    }

    const long long NTOK = (long long)NB * TOKS * TOKD;
    const long long NLAT = (long long)NB * LSEQ * DIM;

    cudaEventRecord(eRoot, 0);
    cudaStreamWaitEvent(s1, eRoot, 0);

    // side stream: latents prep + lat projections
    k_tohalf<<<(int)(NLAT / 4 / 256), 256, 0, s1>>>(latents, latH, NLAT);
    k_prep_wr<<<(DIM * DIM + 255) / 256, 256, 0, s1>>>(W_lat, W_vlat, W_tok, W_vtok, wrH);
    cudaEventRecord(eA, s1);
    k_proj<<<dim3(2 * DIM / BN, (NB * LSEQ) / BM), 256, SM_BYTES, s1>>>(
        latH, wrH, rlatH, vlatT, LSEQ);
    cudaEventRecord(eB, s1);

    // main stream: token prep + conv
    k_tohalf<<<(int)(NTOK / 4 / 256), 256>>>(tokens, toksH, NTOK);
    k_prep_w<<<(DIM * KIN + 255) / 256, 256>>>(conv_w, wcH);
    k_conv<<<dim3(DIM / BN, (NB * SSEQ) / BM), 256, SM_BYTES>>>(toksH, wcH, tok, tokH, conv_b);

    cudaStreamWaitEvent(0, eA, 0);
    k_proj<<<dim3(2 * DIM / BN, (NB * SSEQ) / BM), 256, SM_BYTES>>>(
        tokH, wrH + 2 * DIM * DIM, rtokH, vtokT, SSEQ);

    cudaStreamWaitEvent(0, eB, 0);
    const float scale = 0.044194173824159216f;
    k_scores<<<dim3(SSEQ / BN, LSEQ / BM, NB), 256, SM_BYTES>>>(rlatH, rtokH, scale);

    k_comb<<<(NB * LSEQ + NB * SSEQ) / 256, 256>>>(rmax, rinv, cmax, cinv);
    k_softmax_apply<<<dim3(SSEQ / 64, LSEQ / 32, NB), 256>>>(
        smat, prH, pcTH, rmax, rinv, cmax, cinv);

    k_delta<<<dim3(DIM / BN, 24, NB), 256, SM_BYTES>>>(latents, out);
}

// round 14
// speedup vs baseline: 1.1015x; 1.1015x over previous
#include <cuda_runtime.h>
#include <cuda_fp16.h>
#include <math.h>
#include <stdint.h>

// ---------------- problem constants ----------------
#define NB   8
#define LSEQ 1024
#define SSEQ 2048
#define DIM  512
#define TOKD 256
#define KIN  1280
#define TOKS 10240

// ---------------- scratch ----------------
__device__ __align__(256) __half g_WcH  [DIM * KIN];
__device__ __align__(256) __half g_WrH  [4 * DIM * DIM];   // [Wlat, Wvlat, Wtok, Wvtok]
__device__ __align__(256) __half g_toksH[NB * TOKS * TOKD];
__device__ __align__(256) __half g_latH [NB * LSEQ * DIM];
__device__ __align__(256) float  g_tok  [NB * SSEQ * DIM];
__device__ __align__(256) __half g_tokH [NB * SSEQ * DIM];
__device__ __align__(256) __half g_RlatH[NB * LSEQ * DIM];
__device__ __align__(256) __half g_RtokH[NB * SSEQ * DIM];
__device__ __align__(256) __half g_VlatT[NB * DIM * LSEQ];   // (E, L)
__device__ __align__(256) __half g_VtokT[NB * DIM * SSEQ];   // (E, S)
__device__ __align__(256) __half g_SH   [NB * LSEQ * SSEQ];  // scores, fp16
__device__ __align__(256) __half g_PrH  [NB * LSEQ * SSEQ];
__device__ __align__(256) __half g_PcTH [NB * SSEQ * LSEQ];
__device__ __align__(256) float  g_rmax [NB * LSEQ];
__device__ __align__(256) float  g_rinv [NB * LSEQ];
__device__ __align__(256) float  g_cmax [NB * SSEQ];
__device__ __align__(256) float  g_cinv [NB * SSEQ];
__device__ __align__(256) float  g_prm  [NB * 16 * LSEQ];
__device__ __align__(256) float  g_prs  [NB * 16 * LSEQ];
__device__ __align__(256) float  g_pcm  [NB * 8 * SSEQ];
__device__ __align__(256) float  g_pcs  [NB * 8 * SSEQ];

// ---------------- GEMM config: 128x128 block, 4 warps (64x64 warp tiles) ----------------
#define BM 128
#define BN 128
#define BK 32
#define PH 40
#define STAGES 4
#define ASZH (BM * PH)
#define BSZH (BN * PH)
#define SM_BYTES (STAGES * (ASZH + BSZH) * 2)   // 81920
#define TSTR 136

__device__ __forceinline__ void mma_f16(float c[4], const uint32_t a[4], const uint32_t b[2]) {
    asm volatile(
        "mma.sync.aligned.m16n8k16.row.col.f32.f16.f16.f32 "
        "{%0,%1,%2,%3}, {%4,%5,%6,%7}, {%8,%9}, {%0,%1,%2,%3};"
        : "+f"(c[0]), "+f"(c[1]), "+f"(c[2]), "+f"(c[3])
        : "r"(a[0]), "r"(a[1]), "r"(a[2]), "r"(a[3]), "r"(b[0]), "r"(b[1]));
}

__device__ __forceinline__ void ldsm_x4(uint32_t r[4], uint32_t addr) {
    asm volatile("ldmatrix.sync.aligned.m8n8.x4.shared.b16 {%0,%1,%2,%3}, [%4];"
                 : "=r"(r[0]), "=r"(r[1]), "=r"(r[2]), "=r"(r[3]) : "r"(addr));
}

__device__ __forceinline__ void cpasync16(uint32_t dst, const void* src) {
    asm volatile("cp.async.cg.shared.global [%0], [%1], 16;" :: "r"(dst), "l"(src));
}

__device__ __forceinline__ void msmerge(float& m, float& s, float om, float os) {
    float M = fmaxf(m, om);
    s = s * __expf(m - M) + os * __expf(om - M);
    m = M;
}

// ---------------- shared GEMM mainloop (128 threads, 4 warps, 64x64 tiles) ----------------
__device__ __forceinline__ void gemm_core(
    const __half* __restrict__ A, const __half* __restrict__ B,
    int lda, int ldb, int tiles, int m0, int n0, float (&acc)[4][8][4])
{
    extern __shared__ __half smh[];
    const uint32_t sbase = (uint32_t)__cvta_generic_to_shared(smh);
    const uint32_t aReg = sbase;
    const uint32_t bReg = sbase + STAGES * ASZH * 2;
    const int tid = threadIdx.x;
    const int wid = tid >> 5, lane = tid & 31;
    const int wm = (wid >> 1) * 64, wn = (wid & 1) * 64;

    uint32_t aAddr[4], bAddr[4];
    {
        const int r = lane & 7;
        const int aRowOff = ((lane >> 3) & 1) * 8 + r;
        const int aChunk = lane >> 4;
#pragma unroll
        for (int mi = 0; mi < 4; mi++)
            aAddr[mi] = aReg + (uint32_t)((wm + mi * 16 + aRowOff) * PH + aChunk * 8) * 2;
        const int bRow = (lane >> 4);
        const int bChunk = (lane >> 3) & 1;
#pragma unroll
        for (int p = 0; p < 4; p++)
            bAddr[p] = bReg + (uint32_t)((wn + (2 * p + bRow) * 8 + r) * PH + bChunk * 8) * 2;
    }

#pragma unroll
    for (int i = 0; i < 4; i++)
#pragma unroll
        for (int j = 0; j < 8; j++)
#pragma unroll
            for (int r = 0; r < 4; r++) acc[i][j][r] = 0.f;

    auto loadTile = [&](int t, int buf) {
        const int k0 = t * BK;
        const uint32_t Ab = aReg + buf * ASZH * 2;
        const uint32_t Bb = bReg + buf * BSZH * 2;
#pragma unroll
        for (int i = 0; i < 4; i++) {
            int idx = i * 128 + tid;
            int row = idx >> 2, seg = idx & 3;
            cpasync16(Ab + (uint32_t)(row * PH + seg * 8) * 2,
                      A + (long long)(m0 + row) * lda + k0 + seg * 8);
        }
#pragma unroll
        for (int i = 0; i < 4; i++) {
            int idx = i * 128 + tid;
            int row = idx >> 2, seg = idx & 3;
            cpasync16(Bb + (uint32_t)(row * PH + seg * 8) * 2,
                      B + (long long)(n0 + row) * ldb + k0 + seg * 8);
        }
        asm volatile("cp.async.commit_group;");
    };

    auto compute = [&](int buf) {
        const uint32_t aOff = buf * ASZH * 2;
        const uint32_t bOff = buf * BSZH * 2;
#pragma unroll
        for (int ks = 0; ks < 2; ks++) {
            uint32_t af[4][4], bf[8][2];
#pragma unroll
            for (int mi = 0; mi < 4; mi++)
                ldsm_x4(af[mi], aAddr[mi] + aOff + ks * 32);
#pragma unroll
            for (int p = 0; p < 4; p++) {
                uint32_t t4[4];
                ldsm_x4(t4, bAddr[p] + bOff + ks * 32);
                bf[2 * p][0] = t4[0]; bf[2 * p][1] = t4[1];
                bf[2 * p + 1][0] = t4[2]; bf[2 * p + 1][1] = t4[3];
            }
#pragma unroll
            for (int mi = 0; mi < 4; mi++)
#pragma unroll
                for (int ni = 0; ni < 8; ni++)
                    mma_f16(acc[mi][ni], af[mi], bf[ni]);
        }
    };

    loadTile(0, 0);
    loadTile(1, 1);
    loadTile(2, 2);
    for (int t = 0; t < tiles; t++) {
        if (t + 2 < tiles) asm volatile("cp.async.wait_group 2;");
        else               asm volatile("cp.async.wait_group 0;");
        __syncthreads();
        if (t + 3 < tiles) loadTile(t + 3, (t + 3) & 3);
        compute(t & 3);
    }
}

// ---------------- conv GEMM ----------------
__global__ __launch_bounds__(128, 2) void k_conv(
    const __half* __restrict__ A, const __half* __restrict__ B,
    float* __restrict__ Cf, __half* __restrict__ Ch, const float* __restrict__ bias)
{
    const int m0 = blockIdx.y * BM, n0 = blockIdx.x * BN;
    float acc[4][8][4];
    gemm_core(A, B, KIN, KIN, KIN / BK, m0, n0, acc);
    const int tid = threadIdx.x, wid = tid >> 5, lane = tid & 31;
    const int grp = lane >> 2, tig = lane & 3;
    const int wm = (wid >> 1) * 64, wn = (wid & 1) * 64;
#pragma unroll
    for (int mi = 0; mi < 4; mi++) {
        const int r = m0 + wm + mi * 16 + grp;
#pragma unroll
        for (int ni = 0; ni < 8; ni++) {
            const int c = n0 + wn + ni * 8 + tig * 2;
            float bx = bias[c], by = bias[c + 1];
            float2 v0 = {acc[mi][ni][0] + bx, acc[mi][ni][1] + by};
            float2 v1 = {acc[mi][ni][2] + bx, acc[mi][ni][3] + by};
            *(float2*)(Cf + (long long)r * DIM + c) = v0;
            *(float2*)(Cf + (long long)(r + 8) * DIM + c) = v1;
            *(__half2*)(Ch + (long long)r * DIM + c) = __floats2half2_rn(v0.x, v0.y);
            *(__half2*)(Ch + (long long)(r + 8) * DIM + c) = __floats2half2_rn(v1.x, v1.y);
        }
    }
}

// ---------------- merged R/V projection, V written transposed ----------------
__global__ __launch_bounds__(128, 2) void k_proj(
    const __half* __restrict__ A, const __half* __restrict__ W,
    __half* __restrict__ Rdst, __half* __restrict__ VTdst, int seq)
{
    const int m0 = blockIdx.y * BM, n0 = blockIdx.x * BN;
    float acc[4][8][4];
    gemm_core(A, W, DIM, DIM, DIM / BK, m0, n0, acc);
    const int tid = threadIdx.x, wid = tid >> 5, lane = tid & 31;
    const int grp = lane >> 2, tig = lane & 3;
    const int wm = (wid >> 1) * 64, wn = (wid & 1) * 64;

    if (n0 < DIM) {
#pragma unroll
        for (int mi = 0; mi < 4; mi++) {
            const int r = m0 + wm + mi * 16 + grp;
#pragma unroll
            for (int ni = 0; ni < 8; ni++) {
                const int c = n0 + wn + ni * 8 + tig * 2;
                *(__half2*)(Rdst + (long long)r * DIM + c) =
                    __floats2half2_rn(acc[mi][ni][0], acc[mi][ni][1]);
                *(__half2*)(Rdst + (long long)(r + 8) * DIM + c) =
                    __floats2half2_rn(acc[mi][ni][2], acc[mi][ni][3]);
            }
        }
    } else {
        extern __shared__ __half smh[];
        __syncthreads();
        __half* st = smh;
#pragma unroll
        for (int mi = 0; mi < 4; mi++) {
            const int ml = wm + mi * 16 + grp;
#pragma unroll
            for (int ni = 0; ni < 8; ni++) {
                const int cl = wn + ni * 8 + tig * 2;
                st[(cl + 0) * TSTR + ml]     = __float2half_rn(acc[mi][ni][0]);
                st[(cl + 1) * TSTR + ml]     = __float2half_rn(acc[mi][ni][1]);
                st[(cl + 0) * TSTR + ml + 8] = __float2half_rn(acc[mi][ni][2]);
                st[(cl + 1) * TSTR + ml + 8] = __float2half_rn(acc[mi][ni][3]);
            }
        }
        __syncthreads();
        const int b = m0 / seq;
        const int s0 = m0 - b * seq;
        const int e0 = n0 - DIM;
        __half* VT = VTdst + (long long)b * DIM * seq;
#pragma unroll
        for (int i = 0; i < 64; i++) {
            int idx = i * 128 + tid;
            int cl = idx >> 6, pos = (idx & 63) * 2;
            __half2 v = *(__half2*)(st + cl * TSTR + pos);
            *(__half2*)(VT + (long long)(e0 + cl) * seq + s0 + pos) = v;
        }
    }
}

// ---------------- scores GEMM (fp16 S out) + fused tile-partial stats ----------------
__global__ __launch_bounds__(128, 2) void k_scores(
    const __half* __restrict__ Aall, const __half* __restrict__ Ball, float alpha)
{
    const long long z = blockIdx.z;
    const __half* A = Aall + z * (long long)LSEQ * DIM;
    const __half* B = Ball + z * (long long)SSEQ * DIM;
    __half* Ch = g_SH + z * (long long)LSEQ * SSEQ;
    const int m0 = blockIdx.y * BM, n0 = blockIdx.x * BN;

    float acc[4][8][4];
    gemm_core(A, B, DIM, DIM, DIM / BK, m0, n0, acc);

    const int tid = threadIdx.x, wid = tid >> 5, lane = tid & 31;
    const int grp = lane >> 2, tig = lane & 3;
    const int wm = (wid >> 1) * 64, wn = (wid & 1) * 64;

#pragma unroll
    for (int mi = 0; mi < 4; mi++)
#pragma unroll
        for (int ni = 0; ni < 8; ni++)
#pragma unroll
            for (int r = 0; r < 4; r++) acc[mi][ni][r] *= alpha;
#pragma unroll
    for (int mi = 0; mi < 4; mi++) {
        const int r = m0 + wm + mi * 16 + grp;
#pragma unroll
        for (int ni = 0; ni < 8; ni++) {
            const int c = n0 + wn + ni * 8 + tig * 2;
            *(__half2*)(Ch + (long long)r * SSEQ + c) =
                __floats2half2_rn(acc[mi][ni][0], acc[mi][ni][1]);
            *(__half2*)(Ch + (long long)(r + 8) * SSEQ + c) =
                __floats2half2_rn(acc[mi][ni][2], acc[mi][ni][3]);
        }
    }
    extern __shared__ __half smh[];
    float* smf = (float*)smh;
    __syncthreads();
    // row partials
#pragma unroll
    for (int mi = 0; mi < 4; mi++) {
#pragma unroll
        for (int h = 0; h < 2; h++) {
            float m = -1e30f;
#pragma unroll
            for (int ni = 0; ni < 8; ni++) {
                m = fmaxf(m, acc[mi][ni][2 * h]);
                m = fmaxf(m, acc[mi][ni][2 * h + 1]);
            }
            float s = 0.f;
#pragma unroll
            for (int ni = 0; ni < 8; ni++) {
                s += __expf(acc[mi][ni][2 * h] - m);
                s += __expf(acc[mi][ni][2 * h + 1] - m);
            }
#pragma unroll
            for (int off = 1; off <= 2; off <<= 1) {
                float om = __shfl_xor_sync(0xffffffffu, m, off);
                float os = __shfl_xor_sync(0xffffffffu, s, off);
                msmerge(m, s, om, os);
            }
            if (tig == 0) {
                int lr = mi * 16 + grp + 8 * h;
                smf[(wid * 64 + lr) * 2 + 0] = m;
                smf[(wid * 64 + lr) * 2 + 1] = s;
            }
        }
    }
    __syncthreads();
    if (tid < 128) {
        const int r = tid;
        const int w0 = (r >> 6) * 2, lr = r & 63;
        float m = smf[(w0 * 64 + lr) * 2 + 0];
        float s = smf[(w0 * 64 + lr) * 2 + 1];
        msmerge(m, s, smf[((w0 + 1) * 64 + lr) * 2 + 0], smf[((w0 + 1) * 64 + lr) * 2 + 1]);
        const long long idx = (z * 16 + blockIdx.x) * LSEQ + m0 + r;
        g_prm[idx] = m;
        g_prs[idx] = s;
    }
    __syncthreads();
    // col partials
#pragma unroll
    for (int ni = 0; ni < 8; ni++) {
#pragma unroll
        for (int j = 0; j < 2; j++) {
            float m = -1e30f;
#pragma unroll
            for (int mi = 0; mi < 4; mi++) {
                m = fmaxf(m, acc[mi][ni][j]);
                m = fmaxf(m, acc[mi][ni][2 + j]);
            }
            float s = 0.f;
#pragma unroll
            for (int mi = 0; mi < 4; mi++) {
                s += __expf(acc[mi][ni][j] - m);
                s += __expf(acc[mi][ni][2 + j] - m);
            }
#pragma unroll
            for (int off = 4; off <= 16; off <<= 1) {
                float om = __shfl_xor_sync(0xffffffffu, m, off);
                float os = __shfl_xor_sync(0xffffffffu, s, off);
                msmerge(m, s, om, os);
            }
            if (grp == 0) {
                int lc = ni * 8 + tig * 2 + j;
                smf[(wid * 64 + lc) * 2 + 0] = m;
                smf[(wid * 64 + lc) * 2 + 1] = s;
            }
        }
    }
    __syncthreads();
    if (tid < 128) {
        const int c = tid;
        const int w0 = (c >> 6), lc = c & 63;
        float m = smf[(w0 * 64 + lc) * 2 + 0];
        float s = smf[(w0 * 64 + lc) * 2 + 1];
        msmerge(m, s, smf[((w0 + 2) * 64 + lc) * 2 + 0], smf[((w0 + 2) * 64 + lc) * 2 + 1]);
        const long long idx = (z * 8 + blockIdx.y) * SSEQ + n0 + c;
        g_pcm[idx] = m;
        g_pcs[idx] = s;
    }
}

// ---------------- merged delta GEMM ----------------
__global__ __launch_bounds__(128, 2) void k_delta(
    const float* __restrict__ latents, float* __restrict__ out)
{
    constexpr long long UL = (long long)NB * LSEQ * DIM;
    constexpr long long UT = (long long)NB * SSEQ * DIM;
    constexpr long long CONCAT = UL + UT;

    const long long z = blockIdx.z;
    const __half *A, *Bm;
    const float* addend;
    float *Cf, *Cf2;
    int lda, K, m0;
    if (blockIdx.y < 8) {
        A = g_PrH + z * (long long)LSEQ * SSEQ;  lda = SSEQ; K = SSEQ;
        Bm = g_VtokT + z * (long long)DIM * SSEQ;
        addend = latents + z * (long long)LSEQ * DIM;
        Cf = out + z * (long long)LSEQ * DIM;
        Cf2 = out + CONCAT + z * (long long)(LSEQ + SSEQ) * DIM;
        m0 = blockIdx.y * BM;
    } else {
        A = g_PcTH + z * (long long)SSEQ * LSEQ; lda = LSEQ; K = LSEQ;
        Bm = g_VlatT + z * (long long)DIM * LSEQ;
        addend = g_tok + z * (long long)SSEQ * DIM;
        Cf = out + UL + z * (long long)SSEQ * DIM;
        Cf2 = out + CONCAT + (long long)LSEQ * DIM + z * (long long)(LSEQ + SSEQ) * DIM;
        m0 = (blockIdx.y - 8) * BM;
    }
    const int n0 = blockIdx.x * BN;

    float acc[4][8][4];
    gemm_core(A, Bm, lda, lda, K / BK, m0, n0, acc);

    const int tid = threadIdx.x, wid = tid >> 5, lane = tid & 31;
    const int grp = lane >> 2, tig = lane & 3;
    const int wm = (wid >> 1) * 64, wn = (wid & 1) * 64;
#pragma unroll
    for (int mi = 0; mi < 4; mi++) {
        const int r = m0 + wm + mi * 16 + grp;
#pragma unroll
        for (int ni = 0; ni < 8; ni++) {
            const int c = n0 + wn + ni * 8 + tig * 2;
            float2 a0 = *(const float2*)(addend + (long long)r * DIM + c);
            float2 a1 = *(const float2*)(addend + (long long)(r + 8) * DIM + c);
            float2 v0 = {acc[mi][ni][0] + a0.x, acc[mi][ni][1] + a0.y};
            float2 v1 = {acc[mi][ni][2] + a1.x, acc[mi][ni][3] + a1.y};
            *(float2*)(Cf  + (long long)r * DIM + c) = v0;
            *(float2*)(Cf  + (long long)(r + 8) * DIM + c) = v1;
            *(float2*)(Cf2 + (long long)r * DIM + c) = v0;
            *(float2*)(Cf2 + (long long)(r + 8) * DIM + c) = v1;
        }
    }
}

// ---------------- prep kernels ----------------
__global__ void k_prep_w(const float* __restrict__ w, __half* __restrict__ wc) {
    int i = blockIdx.x * 256 + threadIdx.x;
    if (i < DIM * KIN) {
        int e = i / KIN;
        int r = i - e * KIN;
        int t = r / TOKD;
        int c = r - t * TOKD;
        wc[i] = __float2half_rn(w[e * KIN + c * 5 + t]);
    }
}
__global__ void k_prep_wr(const float* __restrict__ w0, const float* __restrict__ w1,
                          const float* __restrict__ w2, const float* __restrict__ w3,
                          __half* __restrict__ out) {
    int i = blockIdx.x * 256 + threadIdx.x;
    if (i < DIM * DIM) {
        out[i]                 = __float2half_rn(w0[i]);
        out[i + DIM * DIM]     = __float2half_rn(w1[i]);
        out[i + 2 * DIM * DIM] = __float2half_rn(w2[i]);
        out[i + 3 * DIM * DIM] = __float2half_rn(w3[i]);
    }
}
__global__ void k_tohalf(const float* __restrict__ s, __half* __restrict__ d, long long n) {
    long long i = ((long long)blockIdx.x * 256 + threadIdx.x) * 4;
    if (i < n) {
        float4 v = *(const float4*)(s + i);
        *(__half2*)(d + i)     = __floats2half2_rn(v.x, v.y);
        *(__half2*)(d + i + 2) = __floats2half2_rn(v.z, v.w);
    }
}

// ---------------- merged stat combine ----------------
__global__ void k_comb(float* __restrict__ rmax, float* __restrict__ rinv,
                       float* __restrict__ cmax, float* __restrict__ cinv) {
    const int idx = blockIdx.x * 256 + threadIdx.x;
    if (idx < NB * LSEQ) {
        const int b = idx >> 10, l = idx & 1023;
        float m = -1e30f;
#pragma unroll
        for (int t = 0; t < 16; t++) m = fmaxf(m, g_prm[(b * 16 + t) * LSEQ + l]);
        float s = 0.f;
#pragma unroll
        for (int t = 0; t < 16; t++)
            s += g_prs[(b * 16 + t) * LSEQ + l] * __expf(g_prm[(b * 16 + t) * LSEQ + l] - m);
        rmax[idx] = m;
        rinv[idx] = 1.f / s;
    } else {
        const int j = idx - NB * LSEQ;
        const int b = j >> 11, s0 = j & 2047;
        float m = -1e30f;
#pragma unroll
        for (int t = 0; t < 8; t++) m = fmaxf(m, g_pcm[(b * 8 + t) * SSEQ + s0]);
        float s = 0.f;
#pragma unroll
        for (int t = 0; t < 8; t++)
            s += g_pcs[(b * 8 + t) * SSEQ + s0] * __expf(g_pcm[(b * 8 + t) * SSEQ + s0] - m);
        cmax[j] = m;
        cinv[j] = 1.f / s;
    }
}

// ---------------- apply both softmaxes (fp16 S in) -> half ----------------
__global__ __launch_bounds__(256) void k_softmax_apply(
    const __half* __restrict__ A, __half* __restrict__ Pr, __half* __restrict__ PcT,
    const float* __restrict__ rmax, const float* __restrict__ rinv,
    const float* __restrict__ cmax, const float* __restrict__ cinv)
{
    __shared__ float tile[64][33];
    const int b = blockIdx.z;
    const int s0 = blockIdx.x * 64, l0 = blockIdx.y * 32;
    const __half* Ab = A + (long long)b * LSEQ * SSEQ;
    __half* Prb = Pr + (long long)b * LSEQ * SSEQ;
    __half* Pcb = PcT + (long long)b * SSEQ * LSEQ;
    const int lane = threadIdx.x & 31, ty = threadIdx.x >> 5;

    const int sc = s0 + 2 * lane;
    const float2 cm = *(const float2*)(cmax + b * SSEQ + sc);
    const float2 ci = *(const float2*)(cinv + b * SSEQ + sc);
#pragma unroll
    for (int i = 0; i < 4; i++) {
        const int l = l0 + ty + i * 8;
        const float rm = rmax[b * LSEQ + l];
        const float riv = rinv[b * LSEQ + l];
        float2 v = __half22float2(*(const __half2*)(Ab + (long long)l * SSEQ + sc));
        *(__half2*)(Prb + (long long)l * SSEQ + sc) =
            __floats2half2_rn(__expf(v.x - rm) * riv, __expf(v.y - rm) * riv);
        tile[2 * lane][ty + i * 8]     = __expf(v.x - cm.x) * ci.x;
        tile[2 * lane + 1][ty + i * 8] = __expf(v.y - cm.y) * ci.y;
    }
    __syncthreads();
    const int sl = threadIdx.x >> 2;
    const int lo = (threadIdx.x & 3) * 8;
    __half* dst = Pcb + (long long)(s0 + sl) * LSEQ + l0 + lo;
#pragma unroll
    for (int j = 0; j < 8; j += 2)
        *(__half2*)(dst + j) = __floats2half2_rn(tile[sl][lo + j], tile[sl][lo + j + 1]);
}

// ---------------- launch ----------------
extern "C" void kernel_launch(void* const* d_in, const int* in_sizes, int n_in,
                              void* d_out, int out_size) {
    const float* latents = (const float*)d_in[0];
    const float* tokens  = (const float*)d_in[1];
    const float* W_lat   = (const float*)d_in[2];
    const float* W_tok   = (const float*)d_in[3];
    const float* W_vlat  = (const float*)d_in[4];
    const float* W_vtok  = (const float*)d_in[5];
    const float* conv_w  = (const float*)d_in[6];
    const float* conv_b  = (const float*)d_in[7];
    float* out = (float*)d_out;

    __half *wcH, *wrH, *toksH, *latH, *tokH, *rlatH, *rtokH, *vlatT, *vtokT, *prH, *pcTH, *smatH;
    float *tok, *rmax, *rinv, *cmax, *cinv;
    cudaGetSymbolAddress((void**)&wcH,   g_WcH);
    cudaGetSymbolAddress((void**)&wrH,   g_WrH);
    cudaGetSymbolAddress((void**)&toksH, g_toksH);
    cudaGetSymbolAddress((void**)&latH,  g_latH);
    cudaGetSymbolAddress((void**)&tok,   g_tok);
    cudaGetSymbolAddress((void**)&tokH,  g_tokH);
    cudaGetSymbolAddress((void**)&rlatH, g_RlatH);
    cudaGetSymbolAddress((void**)&rtokH, g_RtokH);
    cudaGetSymbolAddress((void**)&vlatT, g_VlatT);
    cudaGetSymbolAddress((void**)&vtokT, g_VtokT);
    cudaGetSymbolAddress((void**)&prH,   g_PrH);
    cudaGetSymbolAddress((void**)&pcTH,  g_PcTH);
    cudaGetSymbolAddress((void**)&smatH, g_SH);
    cudaGetSymbolAddress((void**)&rmax,  g_rmax);
    cudaGetSymbolAddress((void**)&rinv,  g_rinv);
    cudaGetSymbolAddress((void**)&cmax,  g_cmax);
    cudaGetSymbolAddress((void**)&cinv,  g_cinv);

    cudaFuncSetAttribute(k_conv,   cudaFuncAttributeMaxDynamicSharedMemorySize, SM_BYTES);
    cudaFuncSetAttribute(k_proj,   cudaFuncAttributeMaxDynamicSharedMemorySize, SM_BYTES);
    cudaFuncSetAttribute(k_scores, cudaFuncAttributeMaxDynamicSharedMemorySize, SM_BYTES);
    cudaFuncSetAttribute(k_delta,  cudaFuncAttributeMaxDynamicSharedMemorySize, SM_BYTES);

    static cudaStream_t s1 = nullptr;
    static cudaEvent_t eRoot = nullptr, eA = nullptr, eB = nullptr;
    if (s1 == nullptr) {
        cudaStreamCreateWithFlags(&s1, cudaStreamNonBlocking);
        cudaEventCreateWithFlags(&eRoot, cudaEventDisableTiming);
        cudaEventCreateWithFlags(&eA, cudaEventDisableTiming);
        cudaEventCreateWithFlags(&eB, cudaEventDisableTiming);
    }

    const long long NTOK = (long long)NB * TOKS * TOKD;
    const long long NLAT = (long long)NB * LSEQ * DIM;

    cudaEventRecord(eRoot, 0);
    cudaStreamWaitEvent(s1, eRoot, 0);

    // side stream: latents prep + lat projections
    k_tohalf<<<(int)(NLAT / 4 / 256), 256, 0, s1>>>(latents, latH, NLAT);
    k_prep_wr<<<(DIM * DIM + 255) / 256, 256, 0, s1>>>(W_lat, W_vlat, W_tok, W_vtok, wrH);
    cudaEventRecord(eA, s1);
    k_proj<<<dim3(2 * DIM / BN, (NB * LSEQ) / BM), 128, SM_BYTES, s1>>>(
        latH, wrH, rlatH, vlatT, LSEQ);
    cudaEventRecord(eB, s1);

    // main stream: token prep + conv
    k_tohalf<<<(int)(NTOK / 4 / 256), 256>>>(tokens, toksH, NTOK);
    k_prep_w<<<(DIM * KIN + 255) / 256, 256>>>(conv_w, wcH);
    k_conv<<<dim3(DIM / BN, (NB * SSEQ) / BM), 128, SM_BYTES>>>(toksH, wcH, tok, tokH, conv_b);

    cudaStreamWaitEvent(0, eA, 0);
    k_proj<<<dim3(2 * DIM / BN, (NB * SSEQ) / BM), 128, SM_BYTES>>>(
        tokH, wrH + 2 * DIM * DIM, rtokH, vtokT, SSEQ);

    cudaStreamWaitEvent(0, eB, 0);
    const float scale = 0.044194173824159216f;
    k_scores<<<dim3(SSEQ / BN, LSEQ / BM, NB), 128, SM_BYTES>>>(rlatH, rtokH, scale);

    k_comb<<<(NB * LSEQ + NB * SSEQ) / 256, 256>>>(rmax, rinv, cmax, cinv);
    k_softmax_apply<<<dim3(SSEQ / 64, LSEQ / 32, NB), 256>>>(
        smatH, prH, pcTH, rmax, rinv, cmax, cinv);

    k_delta<<<dim3(DIM / BN, 24, NB), 128, SM_BYTES>>>(latents, out);
}